// round 9
// baseline (speedup 1.0000x reference)
#include <cuda_runtime.h>
#include <cuda_bf16.h>
#include <cstdint>
#include <cstddef>

// Problem constants
#define BB 4
#define CC 128
#define NN 4096      // H*W
#define CQ 16
#define TQ 128       // queries per CTA
#define TK 128       // keys per tile
#define NTILES (NN / TK)   // 32

// ---------------------------------------------------------------------------
// Device scratch (bf16 QKV staged between kernels)
// ---------------------------------------------------------------------------
__device__ __align__(16) __nv_bfloat16 g_qb[(size_t)BB * NN * CQ];  // [b][n][cq]
__device__ __align__(16) __nv_bfloat16 g_kb[(size_t)BB * NN * CQ];  // [b][n][cq]
__device__ __align__(16) __nv_bfloat16 g_vb[(size_t)BB * CC * NN];  // [b][c][n]

// ---------------------------------------------------------------------------
// Helpers
// ---------------------------------------------------------------------------
__device__ __forceinline__ uint32_t smem_u32(const void* p) {
    uint32_t a;
    asm("{ .reg .u64 t; cvta.to.shared.u64 t, %1; cvt.u32.u64 %0, t; }"
        : "=r"(a) : "l"(p));
    return a;
}
// pack two fp32 -> bf16x2 (lo in low half)
__device__ __forceinline__ uint32_t pack_bf2(float lo, float hi) {
    uint32_t r;
    asm("cvt.rn.satfinite.bf16x2.f32 %0, %1, %2;" : "=r"(r) : "f"(hi), "f"(lo));
    return r;
}
__device__ __forceinline__ void cp16(uint32_t dst, const void* src) {
    asm volatile("cp.async.cg.shared.global [%0], [%1], 16;"
                 :: "r"(dst), "l"(src));
}
#define CP_COMMIT() asm volatile("cp.async.commit_group;" ::: "memory")
#define CP_WAIT(n)  asm volatile("cp.async.wait_group %0;" :: "n"(n) : "memory")

// mma.m16n8k16 bf16 -> fp32
__device__ __forceinline__ void mma16816(
    float* d,
    uint32_t a0, uint32_t a1, uint32_t a2, uint32_t a3,
    uint32_t b0, uint32_t b1,
    float c0, float c1, float c2, float c3)
{
    asm volatile(
        "mma.sync.aligned.m16n8k16.row.col.f32.bf16.bf16.f32 "
        "{%0,%1,%2,%3}, {%4,%5,%6,%7}, {%8,%9}, {%10,%11,%12,%13};"
        : "=f"(d[0]), "=f"(d[1]), "=f"(d[2]), "=f"(d[3])
        : "r"(a0), "r"(a1), "r"(a2), "r"(a3),
          "r"(b0), "r"(b1),
          "f"(c0), "f"(c1), "f"(c2), "f"(c3));
}

// ---------------------------------------------------------------------------
// Kernel 1: fused QKV 1x1 convs as one smem-tiled GEMM. (unchanged from R8)
// ---------------------------------------------------------------------------
#define WPITCH 132
#define QKV_SMEM (128 * WPITCH * 4 + 128 * 32 * 4 + 2 * 16 * 128 * 4)

__global__ void __launch_bounds__(256, 1) qkv_kernel(
    const float* __restrict__ x,
    const float* __restrict__ wq, const float* __restrict__ bq,
    const float* __restrict__ wk, const float* __restrict__ bk,
    const float* __restrict__ wv, const float* __restrict__ bv)
{
    extern __shared__ float s[];
    float* w_st  = s;                       // [128 k][WPITCH]
    float* wqk   = s + 128 * WPITCH;        // [128 k][32]
    float* x_s   = wqk + 128 * 32;          // [2][16][128]
    const uint32_t xsb = smem_u32(x_s);

    const int tid = threadIdx.x;
    const int b   = blockIdx.y;
    const int n0  = blockIdx.x * 128;
    const int ti  = tid & 15;
    const int tj  = tid >> 4;
    const int c0  = tj * 8;
    const int nb  = ti * 8;
    const int r0  = tj * 2;

    for (int i = tid; i < CC * CC; i += 256) {
        const int c = i >> 7, k = i & 127;
        w_st[k * WPITCH + c] = wv[i];
    }
    for (int i = tid; i < CQ * CC; i += 256) {
        const int r = i >> 7, k = i & 127;
        wqk[k * 32 + r]      = wq[i];
        wqk[k * 32 + 16 + r] = wk[i];
    }

    const float* xb = x + (size_t)b * CC * NN + n0;

#pragma unroll
    for (int it = 0; it < 2; ++it) {
        const int i = tid + it * 256;
        const int r = i >> 5, cc = (i & 31) * 4;
        cp16(xsb + (uint32_t)(r * 128 + cc) * 4, xb + (size_t)r * NN + cc);
    }
    CP_COMMIT();

    float acc[8][8];
    float qkacc[2][8];
#pragma unroll
    for (int j = 0; j < 8; ++j) {
        qkacc[0][j] = 0.f; qkacc[1][j] = 0.f;
#pragma unroll
        for (int k = 0; k < 8; ++k) acc[j][k] = 0.f;
    }

    for (int t = 0; t < 8; ++t) {
        if (t + 1 < 8) {
            const uint32_t dst = xsb + (uint32_t)(((t + 1) & 1) * 2048) * 4;
#pragma unroll
            for (int it = 0; it < 2; ++it) {
                const int i = tid + it * 256;
                const int r = i >> 5, cc = (i & 31) * 4;
                cp16(dst + (uint32_t)(r * 128 + cc) * 4,
                     xb + (size_t)(16 * (t + 1) + r) * NN + cc);
            }
            CP_COMMIT();
            CP_WAIT(1);
        } else {
            CP_WAIT(0);
        }
        __syncthreads();

        const float* xs   = x_s + (t & 1) * 2048;
        const float* wkp  = w_st + 16 * t * WPITCH;
        const float* wqkp = wqk + 16 * t * 32;
#pragma unroll
        for (int kk = 0; kk < 16; ++kk) {
            const float4 w0 = *(const float4*)(wkp + kk * WPITCH + c0);
            const float4 w1 = *(const float4*)(wkp + kk * WPITCH + c0 + 4);
            const float  u0 = wqkp[kk * 32 + r0];
            const float  u1 = wqkp[kk * 32 + r0 + 1];
            const float4 x0 = *(const float4*)(xs + kk * 128 + nb);
            const float4 x1 = *(const float4*)(xs + kk * 128 + nb + 4);
            const float wr[8] = {w0.x, w0.y, w0.z, w0.w, w1.x, w1.y, w1.z, w1.w};
            const float xr[8] = {x0.x, x0.y, x0.z, x0.w, x1.x, x1.y, x1.z, x1.w};
#pragma unroll
            for (int k = 0; k < 8; ++k) {
                qkacc[0][k] += u0 * xr[k];
                qkacc[1][k] += u1 * xr[k];
#pragma unroll
                for (int j = 0; j < 8; ++j)
                    acc[j][k] += wr[j] * xr[k];
            }
        }
        __syncthreads();
    }

#pragma unroll
    for (int j = 0; j < 8; ++j) {
        const float bb = bv[c0 + j];
        uint4 u;
        u.x = pack_bf2(acc[j][0] + bb, acc[j][1] + bb);
        u.y = pack_bf2(acc[j][2] + bb, acc[j][3] + bb);
        u.z = pack_bf2(acc[j][4] + bb, acc[j][5] + bb);
        u.w = pack_bf2(acc[j][6] + bb, acc[j][7] + bb);
        *(uint4*)((char*)g_vb + (((size_t)b * CC + c0 + j) * NN + n0 + nb) * 2) = u;
    }

    {
        const float bias0 = (r0 < 16) ? __ldg(bq + r0) : __ldg(bk + r0 - 16);
        const float bias1 = (r0 + 1 < 16) ? __ldg(bq + r0 + 1) : __ldg(bk + r0 - 15);
        float* qk_s = x_s;                  // [32 rows][128 n]
#pragma unroll
        for (int k = 0; k < 8; ++k) {
            qk_s[r0 * 128 + nb + k]       = qkacc[0][k] + bias0;
            qk_s[(r0 + 1) * 128 + nb + k] = qkacc[1][k] + bias1;
        }
        __syncthreads();

        const int half = tid >> 7;          // 0: q, 1: k
        const int nl   = tid & 127;
        const int rb   = half * 16;
        uint32_t pk[8];
#pragma unroll
        for (int j = 0; j < 8; ++j)
            pk[j] = pack_bf2(qk_s[(rb + 2 * j) * 128 + nl],
                             qk_s[(rb + 2 * j + 1) * 128 + nl]);
        char* dst = (char*)(half ? g_kb : g_qb) + ((size_t)b * NN + n0 + nl) * 32;
        *(uint4*)(dst)      = make_uint4(pk[0], pk[1], pk[2], pk[3]);
        *(uint4*)(dst + 16) = make_uint4(pk[4], pk[5], pk[6], pk[7]);
    }
}

// ---------------------------------------------------------------------------
// Kernel 2: HMMA flash attention, 2D warp split.
// 8 warps = 4 query-groups (32 q = 2 row blocks) x 2 key-halves (64 keys/tile).
// Each V fragment load feeds 2 row blocks AND each warp touches only half the
// s-steps -> V crossbar traffic per query halves vs R8.
// End: kh=1 warps dump partial O/l to smem; kh=0 warps combine + write.
// smem: Q [128][48] 6144 | K0/K1 6144 | V0/V1 [128c][272] 34816 ea. 88064 B.
// (O_s scratch [128][132] fp32 + l_s [128] reuses the dead K/V region.)
// ---------------------------------------------------------------------------
#define KPITCH 48
#define VPITCH 272
#define SM_Q   0
#define SM_K0  6144
#define SM_K1  12288
#define SM_V0  18432
#define SM_V1  (SM_V0 + 34816)
#define SM_TOTAL (SM_V1 + 34816)
#define OSPITCH 132
#define SM_LS   (128 * OSPITCH * 4)   // 67584; + 512 = 68096 <= SM_TOTAL

__device__ __forceinline__ void issue_tile(
    uint32_t smb, const char* kg, const char* vg, int t, int buf, int tid)
{
    const uint32_t kdst = smb + (buf ? SM_K1 : SM_K0);
    const uint32_t vdst = smb + (buf ? SM_V1 : SM_V0);
    const int m0 = t * TK;
    {   // K tile: 128 rows x 32B = 256 x 16B chunks
        const int n = tid >> 1, h = tid & 1;
        cp16(kdst + n * KPITCH + h * 16, kg + (size_t)(m0 + n) * 32 + h * 16);
    }
#pragma unroll
    for (int it = 0; it < 8; ++it) {  // V: 2048 x 16B chunks
        const int i = tid + it * 256;
        const int c = i >> 4, h = i & 15;
        cp16(vdst + c * VPITCH + h * 16,
             vg + (size_t)c * (NN * 2) + (size_t)m0 * 2 + h * 16);
    }
}

__global__ void __launch_bounds__(256, 1) attn_kernel(
    const float* __restrict__ x,
    const float* __restrict__ gamma,
    float* __restrict__ out)
{
    extern __shared__ char sm[];
    const uint32_t smb = smem_u32(sm);
    const int tid  = threadIdx.x;
    const int w    = tid >> 5;
    const int lane = tid & 31;
    const int p    = lane >> 2;      // row group
    const int q    = lane & 3;       // col pair
    const int qg   = w & 3;          // query group (32 queries)
    const int kh   = w >> 2;         // key half (s-steps 4kh..4kh+3)

    const int b  = blockIdx.y;
    const int n0 = blockIdx.x * TQ;

    const char* qg_p = (const char*)g_qb + ((size_t)b * NN + n0) * 32;
    const char* kg_p = (const char*)g_kb + (size_t)b * NN * 32;
    const char* vg_p = (const char*)g_vb + (size_t)b * CC * NN * 2;

    // ---- load Q tile (plain), issue K/V tile 0 ----
    {
        const int r = tid >> 1, h = tid & 1;
        *(uint4*)(sm + SM_Q + r * KPITCH + h * 16) =
            *(const uint4*)(qg_p + r * 32 + h * 16);
    }
    issue_tile(smb, kg_p, vg_p, 0, 0, tid);
    CP_COMMIT();
    __syncthreads();

    // ---- Q A-fragments for both row blocks ----
    uint32_t qa[2][4];
#pragma unroll
    for (int rb = 0; rb < 2; ++rb) {
        const int r = 32 * qg + 16 * rb + p;
        qa[rb][0] = *(const uint32_t*)(sm + SM_Q + r       * KPITCH + 4 * q);
        qa[rb][1] = *(const uint32_t*)(sm + SM_Q + (r + 8) * KPITCH + 4 * q);
        qa[rb][2] = *(const uint32_t*)(sm + SM_Q + r       * KPITCH + 16 + 4 * q);
        qa[rb][3] = *(const uint32_t*)(sm + SM_Q + (r + 8) * KPITCH + 16 + 4 * q);
    }

    float o[2][16][4];
#pragma unroll
    for (int rb = 0; rb < 2; ++rb)
#pragma unroll
        for (int jc = 0; jc < 16; ++jc)
#pragma unroll
            for (int k = 0; k < 4; ++k) o[rb][jc][k] = 0.f;
    float lsum[2][2] = {{0.f, 0.f}, {0.f, 0.f}};

    for (int t = 0; t < NTILES; ++t) {
        if (t + 1 < NTILES) {
            issue_tile(smb, kg_p, vg_p, t + 1, (t + 1) & 1, tid);
            CP_COMMIT();
            CP_WAIT(1);
        } else {
            CP_WAIT(0);
        }
        __syncthreads();

        const char* smK = sm + ((t & 1) ? SM_K1 : SM_K0);
        const char* smV = sm + ((t & 1) ? SM_V1 : SM_V0);

#pragma unroll
        for (int sl = 0; sl < 4; ++sl) {
            const int s = 4 * kh + sl;
            // ---- K fragments (shared by both row blocks) ----
            const char* kr0 = smK + (16 * s + p)     * KPITCH + 4 * q;
            const char* kr1 = smK + (16 * s + 8 + p) * KPITCH + 4 * q;
            const uint32_t bka0 = *(const uint32_t*)(kr0);
            const uint32_t bka1 = *(const uint32_t*)(kr0 + 16);
            const uint32_t bkb0 = *(const uint32_t*)(kr1);
            const uint32_t bkb1 = *(const uint32_t*)(kr1 + 16);

            uint32_t pa[2][4];
#pragma unroll
            for (int rb = 0; rb < 2; ++rb) {
                float d[8];
                mma16816(d,     qa[rb][0], qa[rb][1], qa[rb][2], qa[rb][3],
                         bka0, bka1, 0.f, 0.f, 0.f, 0.f);
                mma16816(d + 4, qa[rb][0], qa[rb][1], qa[rb][2], qa[rb][3],
                         bkb0, bkb1, 0.f, 0.f, 0.f, 0.f);

                const float e0 = __expf(d[0]), e1 = __expf(d[1]);
                const float e2 = __expf(d[2]), e3 = __expf(d[3]);
                const float e4 = __expf(d[4]), e5 = __expf(d[5]);
                const float e6 = __expf(d[6]), e7 = __expf(d[7]);
                lsum[rb][0] += (e0 + e1) + (e4 + e5);
                lsum[rb][1] += (e2 + e3) + (e6 + e7);
                pa[rb][0] = pack_bf2(e0, e1);
                pa[rb][1] = pack_bf2(e2, e3);
                pa[rb][2] = pack_bf2(e4, e5);
                pa[rb][3] = pack_bf2(e6, e7);
            }

            // ---- MMA2: V fragment shared across both row blocks ----
#pragma unroll
            for (int jc = 0; jc < 16; ++jc) {
                const char* vr = smV + (8 * jc + p) * VPITCH + 32 * s + 4 * q;
                const uint32_t bv0 = *(const uint32_t*)(vr);
                const uint32_t bv1 = *(const uint32_t*)(vr + 16);
                mma16816(o[0][jc], pa[0][0], pa[0][1], pa[0][2], pa[0][3],
                         bv0, bv1, o[0][jc][0], o[0][jc][1], o[0][jc][2], o[0][jc][3]);
                mma16816(o[1][jc], pa[1][0], pa[1][1], pa[1][2], pa[1][3],
                         bv0, bv1, o[1][jc][0], o[1][jc][1], o[1][jc][2], o[1][jc][3]);
            }
        }
        __syncthreads();
    }

    // ---- quad-reduce partial l (within row groups) ----
#pragma unroll
    for (int rb = 0; rb < 2; ++rb)
#pragma unroll
        for (int g2 = 0; g2 < 2; ++g2) {
            lsum[rb][g2] += __shfl_xor_sync(0xffffffffu, lsum[rb][g2], 1);
            lsum[rb][g2] += __shfl_xor_sync(0xffffffffu, lsum[rb][g2], 2);
        }

    // ---- cross-key-half combine through smem ----
    float* O_s = (float*)sm;                 // [128 rows][OSPITCH]
    float* l_s = (float*)(sm + SM_LS);       // [128]

    if (kh == 1) {
#pragma unroll
        for (int rb = 0; rb < 2; ++rb) {
            const int rr = 32 * qg + 16 * rb + p;
#pragma unroll
            for (int jc = 0; jc < 16; ++jc) {
                const int c = 8 * jc + 2 * q;
                O_s[rr * OSPITCH + c]           = o[rb][jc][0];
                O_s[rr * OSPITCH + c + 1]       = o[rb][jc][1];
                O_s[(rr + 8) * OSPITCH + c]     = o[rb][jc][2];
                O_s[(rr + 8) * OSPITCH + c + 1] = o[rb][jc][3];
            }
            if (q == 0) {
                l_s[rr]     = lsum[rb][0];
                l_s[rr + 8] = lsum[rb][1];
            }
        }
    }
    __syncthreads();

    if (kh == 0) {
        const float g = __ldg(gamma);
#pragma unroll
        for (int rb = 0; rb < 2; ++rb) {
            const int rr   = 32 * qg + 16 * rb + p;
            const float inv0 = 1.f / (lsum[rb][0] + l_s[rr]);
            const float inv1 = 1.f / (lsum[rb][1] + l_s[rr + 8]);
            const int nrow = n0 + rr;
#pragma unroll
            for (int jc = 0; jc < 16; ++jc) {
                const int c = 8 * jc + 2 * q;
                const float v0 = (o[rb][jc][0] + O_s[rr * OSPITCH + c])           * inv0;
                const float v1 = (o[rb][jc][1] + O_s[rr * OSPITCH + c + 1])       * inv0;
                const float v2 = (o[rb][jc][2] + O_s[(rr + 8) * OSPITCH + c])     * inv1;
                const float v3 = (o[rb][jc][3] + O_s[(rr + 8) * OSPITCH + c + 1]) * inv1;
                const size_t i0 = ((size_t)b * CC + c) * NN + nrow;
                out[i0]          = g * v0 + x[i0];
                out[i0 + NN]     = g * v1 + x[i0 + NN];
                out[i0 + 8]      = g * v2 + x[i0 + 8];
                out[i0 + NN + 8] = g * v3 + x[i0 + NN + 8];
            }
        }
    }
}

// ---------------------------------------------------------------------------
// Launch
// ---------------------------------------------------------------------------
extern "C" void kernel_launch(void* const* d_in, const int* in_sizes, int n_in,
                              void* d_out, int out_size)
{
    const float* x     = (const float*)d_in[0];
    const float* wq    = (const float*)d_in[1];
    const float* bq    = (const float*)d_in[2];
    const float* wk    = (const float*)d_in[3];
    const float* bk    = (const float*)d_in[4];
    const float* wv    = (const float*)d_in[5];
    const float* bv    = (const float*)d_in[6];
    const float* gamma = (const float*)d_in[7];
    float* out = (float*)d_out;
    (void)in_sizes; (void)n_in; (void)out_size;

    cudaFuncSetAttribute(qkv_kernel,
                         cudaFuncAttributeMaxDynamicSharedMemorySize, QKV_SMEM);
    qkv_kernel<<<dim3(NN / 128, BB), 256, QKV_SMEM>>>(x, wq, bq, wk, bk, wv, bv);

    cudaFuncSetAttribute(attn_kernel,
                         cudaFuncAttributeMaxDynamicSharedMemorySize, SM_TOTAL);
    attn_kernel<<<dim3(NN / TQ, BB), 256, SM_TOTAL>>>(x, gamma, out);
}